// round 17
// baseline (speedup 1.0000x reference)
#include <cuda_runtime.h>
#include <cuda_bf16.h>
#include <cstdint>
#include <cmath>

#define NROWS 8192
#define XROWS 16384
#define DIM   64
#define BT    128                 // tile dim
#define NT    (XROWS / BT)        // 128 tiles per side
#define NTRI  (NT * (NT + 1) / 2) // 8256 upper-triangle tiles (column-major order)
#define LPAD  72                  // padded smem row stride (bf16 elems)
#define ROWB  (LPAD * 2)          // 144 bytes per smem row
#define TILEB (BT * ROWB)         // 18432 bytes per operand tile
#define CPOFF (4 * TILEB)         // colpart offset: 73728 (2x Ls + 2x Rs buffers)
#define CPAD  132                 // colpart row stride (floats)
#define SMEM_TOTAL (CPOFF + 64 * CPAD * 4)   // 107520 bytes (2 CTAs/SM)

#define SCALE_L2E 28.853900817779268f   // 20 * log2(e)

// ---------------- device scratch ----------------
__device__ __align__(16) __nv_bfloat16 g_Xs[XROWS * DIM];  // normalized * 20*log2(e)
__device__ __align__(16) __nv_bfloat16 g_Xn[XROWS * DIM];  // normalized
__device__ float g_part[XROWS];
__device__ float g_pos[NROWS];
__device__ int   g_done;

static __device__ __forceinline__ uint32_t smem_u32(const void* p) {
    uint32_t a;
    asm("{ .reg .u64 t; cvta.to.shared.u64 t, %1; cvt.u32.u64 %0, t; }" : "=r"(a) : "l"(p));
    return a;
}
static __device__ __forceinline__ float ex2f(float x) {
    float y; asm volatile("ex2.approx.ftz.f32 %0, %1;" : "=f"(y) : "f"(x)); return y;
}
static __device__ __forceinline__ void cp16(uint32_t dst, const void* src) {
    asm volatile("cp.async.cg.shared.global [%0], [%1], 16;" :: "r"(dst), "l"(src) : "memory");
}
// column-major triangle: t = bj*(bj+1)/2 + bi, 0 <= bi <= bj
static __device__ __forceinline__ int col_of(int t) {
    int bj = (int)((sqrtf(8.0f * (float)t + 1.0f) - 1.0f) * 0.5f);
    if (bj < 0) bj = 0;
    if (bj > NT - 1) bj = NT - 1;
    while (bj * (bj + 1) / 2 > t) --bj;
    while ((bj + 1) * (bj + 2) / 2 <= t) ++bj;
    return bj;
}

// ---------------- kernel 1: normalize + bf16 + exact pos logit + zeroing (2 rows/warp) ----------------
__global__ void prep_kernel(const float* __restrict__ A, const float* __restrict__ P,
                            float* __restrict__ out) {
    int r0   = blockIdx.x * 16 + (threadIdx.x >> 5) * 2;
    int lane = threadIdx.x & 31;
    #pragma unroll
    for (int rr = 0; rr < 2; ++rr) {
        int row = r0 + rr;
        float a0 = A[(size_t)row * DIM + lane], a1 = A[(size_t)row * DIM + lane + 32];
        float p0 = P[(size_t)row * DIM + lane], p1 = P[(size_t)row * DIM + lane + 32];
        float sa = a0 * a0 + a1 * a1;
        float sp = p0 * p0 + p1 * p1;
        float d  = a0 * p0 + a1 * p1;
        #pragma unroll
        for (int o = 16; o; o >>= 1) {
            sa += __shfl_xor_sync(0xffffffffu, sa, o);
            sp += __shfl_xor_sync(0xffffffffu, sp, o);
            d  += __shfl_xor_sync(0xffffffffu, d,  o);
        }
        float ra = rsqrtf(fmaxf(sa, 1e-24f));
        float rp = rsqrtf(fmaxf(sp, 1e-24f));
        float va0 = a0 * ra, va1 = a1 * ra;
        float vp0 = p0 * rp, vp1 = p1 * rp;
        size_t ia = (size_t)row * DIM, ip = (size_t)(row + NROWS) * DIM;
        g_Xn[ia + lane]      = __float2bfloat16(va0);
        g_Xn[ia + lane + 32] = __float2bfloat16(va1);
        g_Xn[ip + lane]      = __float2bfloat16(vp0);
        g_Xn[ip + lane + 32] = __float2bfloat16(vp1);
        g_Xs[ia + lane]      = __float2bfloat16(va0 * SCALE_L2E);
        g_Xs[ia + lane + 32] = __float2bfloat16(va1 * SCALE_L2E);
        g_Xs[ip + lane]      = __float2bfloat16(vp0 * SCALE_L2E);
        g_Xs[ip + lane + 32] = __float2bfloat16(vp1 * SCALE_L2E);
        if (lane == 0) {
            g_pos[row] = 20.0f * d / fmaxf(sqrtf(sa) * sqrtf(sp), 1e-6f);
            g_part[row] = 0.0f;
            g_part[row + NROWS] = 0.0f;
        }
    }
    if (blockIdx.x == 0 && threadIdx.x == 0) { out[0] = 0.0f; g_done = 0; }
}

// one exp+mask+accumulate unit of the PREVIOUS n2 iteration (compile-time indices)
#define EXP_UNIT(n2p, pu, pe)                                                    \
    do {                                                                         \
        float e = ex2f(cp[pu][pe]);                                              \
        if (diag) {                                                              \
            int gc = gcol0 + ((n2p) * 2 + (pu)) * 8 + tig * 2 + ((pe) & 1);      \
            int rr = ((pe) < 2) ? myrow0 : myrow1;                               \
            if (gc <= rr) e = 0.0f;                                              \
        }                                                                        \
        if ((pe) < 2) row0s += e; else row1s += e;                               \
        cs[(n2p) * 2 + (pu)][(pe) & 1] += e;                                     \
    } while (0)

// ---------------- kernel 2: persistent column-major triangle GEMM + fused final loss ----------------
// R13 structure; n2 mainloop software-pipelined: each HMMA of iteration n2 is
// followed by one exp/accumulate unit of iteration n2-1, feeding the tensor and
// MUFU pipes concurrently instead of in alternating phases.
__global__ void __launch_bounds__(256, 2) mma_kernel(int Q, int R, int G,
                                                     float* __restrict__ out) {
    extern __shared__ __align__(16) unsigned char smem[];
    uint32_t sbase = smem_u32(smem);        // Ls buffers at 0, TILEB; Rs at 2*TILEB, 3*TILEB
    float* colpart = (float*)(smem + CPOFF);

    int c = blockIdx.x;
    int t0 = c * Q + min(c, R);
    int t1 = t0 + Q + (c < R ? 1 : 0);

    int tid = threadIdx.x, wid = tid >> 5, lane = tid & 31;
    int gid = lane >> 2, tig = lane & 3;
    int b_u = (lane >> 4) & 1;
    int b_h = (lane >> 3) & 1;
    int b_r = lane & 7;

    if (t0 < t1) {
        int bj = col_of(t0);
        int bi = t0 - bj * (bj + 1) / 2;
        int lbuf = 0, rbuf = 0;

        {   // prefetch first Ls + Rs
            const uint4* Lg = (const uint4*)(g_Xs + (size_t)bi * BT * DIM);
            const uint4* Rg = (const uint4*)(g_Xn + (size_t)bj * BT * DIM);
            #pragma unroll
            for (int it = 0; it < 4; ++it) {
                int f = tid + it * 256;
                uint32_t off = (uint32_t)(f >> 3) * ROWB + (uint32_t)(f & 7) * 16;
                cp16(sbase + off, Lg + f);
                cp16(sbase + 2 * TILEB + off, Rg + f);
            }
            asm volatile("cp.async.commit_group;" ::: "memory");
        }

        float cs[16][2];
        #pragma unroll
        for (int i = 0; i < 16; ++i) { cs[i][0] = 0.0f; cs[i][1] = 0.0f; }

        for (int t = t0; t < t1; ++t) {
            bool hasn = (t + 1 < t1);
            int bin = bi, bjn = bj;
            bool colchg = false;
            if (hasn) {
                if (bi < bj) { bin = bi + 1; }
                else         { bjn = bj + 1; bin = 0; colchg = true; }
                const uint4* Lg = (const uint4*)(g_Xs + (size_t)bin * BT * DIM);
                uint32_t lb = sbase + (uint32_t)(lbuf ^ 1) * TILEB;
                const uint4* Rg = (const uint4*)(g_Xn + (size_t)bjn * BT * DIM);
                uint32_t rb = sbase + (uint32_t)(2 + (rbuf ^ 1)) * TILEB;
                #pragma unroll
                for (int it = 0; it < 4; ++it) {
                    int f = tid + it * 256;
                    uint32_t off = (uint32_t)(f >> 3) * ROWB + (uint32_t)(f & 7) * 16;
                    cp16(lb + off, Lg + f);
                    if (colchg) cp16(rb + off, Rg + f);
                }
                asm volatile("cp.async.commit_group;" ::: "memory");
                asm volatile("cp.async.wait_group 1;" ::: "memory");
            } else {
                asm volatile("cp.async.wait_group 0;" ::: "memory");
            }
            __syncthreads();

            uint32_t Lbase = sbase + (uint32_t)lbuf * TILEB;
            uint32_t Rbase = sbase + (uint32_t)(2 + rbuf) * TILEB;
            bool diag = (bi == bj);
            int grow0 = bi * BT, gcol0 = bj * BT;

            uint32_t a[4][4];
            {
                int r  = wid * 16 + (lane & 15);
                int kh = (lane >> 4) * 8;
                #pragma unroll
                for (int kc = 0; kc < 4; ++kc) {
                    uint32_t addr = Lbase + (uint32_t)r * ROWB + (uint32_t)(kc * 16 + kh) * 2;
                    asm volatile("ldmatrix.sync.aligned.m8n8.x4.shared.b16 {%0,%1,%2,%3}, [%4];"
                                 : "=r"(a[kc][0]), "=r"(a[kc][1]), "=r"(a[kc][2]), "=r"(a[kc][3])
                                 : "r"(addr));
                }
            }

            int myrow0 = grow0 + wid * 16 + gid;
            int myrow1 = myrow0 + 8;
            float row0s = 0.0f, row1s = 0.0f;

            // ---- software-pipelined n2 loop ----
            float cp[2][4];                 // previous iteration's accumulators

            // n2 = 0: MMA only
            {
                uint32_t b[2][4][2];
                #pragma unroll
                for (int kc = 0; kc < 4; ++kc) {
                    uint32_t addr = Rbase + (uint32_t)(b_u * 8 + b_r) * ROWB
                                  + (uint32_t)(kc * 16 + b_h * 8) * 2;
                    asm volatile("ldmatrix.sync.aligned.m8n8.x4.shared.b16 {%0,%1,%2,%3}, [%4];"
                                 : "=r"(b[0][kc][0]), "=r"(b[0][kc][1]),
                                   "=r"(b[1][kc][0]), "=r"(b[1][kc][1])
                                 : "r"(addr));
                }
                float cc[2][4] = {};
                #pragma unroll
                for (int kc = 0; kc < 4; ++kc) {
                    #pragma unroll
                    for (int u = 0; u < 2; ++u) {
                        asm volatile(
                            "mma.sync.aligned.m16n8k16.row.col.f32.bf16.bf16.f32 "
                            "{%0,%1,%2,%3}, {%4,%5,%6,%7}, {%8,%9}, {%0,%1,%2,%3};"
                            : "+f"(cc[u][0]), "+f"(cc[u][1]), "+f"(cc[u][2]), "+f"(cc[u][3])
                            : "r"(a[kc][0]), "r"(a[kc][1]), "r"(a[kc][2]), "r"(a[kc][3]),
                              "r"(b[u][kc][0]), "r"(b[u][kc][1]));
                    }
                }
                #pragma unroll
                for (int u = 0; u < 2; ++u)
                    #pragma unroll
                    for (int k = 0; k < 4; ++k) cp[u][k] = cc[u][k];
            }

            // n2 = 1..7: MMA(n2) with exp(n2-1) interleaved after each HMMA
            #pragma unroll
            for (int n2 = 1; n2 < 8; ++n2) {
                uint32_t b[2][4][2];
                #pragma unroll
                for (int kc = 0; kc < 4; ++kc) {
                    uint32_t addr = Rbase + (uint32_t)(n2 * 16 + b_u * 8 + b_r) * ROWB
                                  + (uint32_t)(kc * 16 + b_h * 8) * 2;
                    asm volatile("ldmatrix.sync.aligned.m8n8.x4.shared.b16 {%0,%1,%2,%3}, [%4];"
                                 : "=r"(b[0][kc][0]), "=r"(b[0][kc][1]),
                                   "=r"(b[1][kc][0]), "=r"(b[1][kc][1])
                                 : "r"(addr));
                }
                float cc[2][4] = {};
                #pragma unroll
                for (int kc = 0; kc < 4; ++kc) {
                    #pragma unroll
                    for (int u = 0; u < 2; ++u) {
                        asm volatile(
                            "mma.sync.aligned.m16n8k16.row.col.f32.bf16.bf16.f32 "
                            "{%0,%1,%2,%3}, {%4,%5,%6,%7}, {%8,%9}, {%0,%1,%2,%3};"
                            : "+f"(cc[u][0]), "+f"(cc[u][1]), "+f"(cc[u][2]), "+f"(cc[u][3])
                            : "r"(a[kc][0]), "r"(a[kc][1]), "r"(a[kc][2]), "r"(a[kc][3]),
                              "r"(b[u][kc][0]), "r"(b[u][kc][1]));
                        // one exp unit of iteration n2-1: element idx = kc*2+u
                        EXP_UNIT(n2 - 1, (kc * 2 + u) >> 2, (kc * 2 + u) & 3);
                    }
                }
                #pragma unroll
                for (int u = 0; u < 2; ++u)
                    #pragma unroll
                    for (int k = 0; k < 4; ++k) cp[u][k] = cc[u][k];
            }

            // epilogue: exp units for n2 = 7
            #pragma unroll
            for (int idx = 0; idx < 8; ++idx)
                EXP_UNIT(7, idx >> 2, idx & 3);

            // row flush: 4 shfl + 2 spread atomics
            #pragma unroll
            for (int o = 1; o < 4; o <<= 1) {
                row0s += __shfl_xor_sync(0xffffffffu, row0s, o);
                row1s += __shfl_xor_sync(0xffffffffu, row1s, o);
            }
            if (tig == 0) {
                atomicAdd(&g_part[myrow0], row0s);
                atomicAdd(&g_part[myrow1], row1s);
            }

            // col flush at end of column (or end of range)
            if (!hasn || colchg) {
                __syncthreads();
                int slice = wid * 8 + gid;
                #pragma unroll
                for (int ci = 0; ci < 16; ++ci)
                    *(float2*)&colpart[slice * CPAD + ci * 8 + tig * 2] =
                        make_float2(cs[ci][0], cs[ci][1]);
                __syncthreads();
                int col = tid & 127, h = tid >> 7;
                float s = 0.0f;
                #pragma unroll
                for (int k = 0; k < 32; ++k) s += colpart[(h * 32 + k) * CPAD + col];
                atomicAdd(&g_part[bj * BT + col], s);
                #pragma unroll
                for (int i = 0; i < 16; ++i) { cs[i][0] = 0.0f; cs[i][1] = 0.0f; }
            }

            if (hasn) {
                lbuf ^= 1;
                if (colchg) rbuf ^= 1;
                bi = bin; bj = bjn;
            }
        }
    }

    // ---- fused loss: last CTA reduces g_part -> out[0] ----
    __shared__ int slast;
    __shared__ float wsum[8];
    __threadfence();
    if (tid == 0) slast = (atomicAdd(&g_done, 1) == G - 1) ? 1 : 0;
    __syncthreads();
    if (slast) {
        __threadfence();
        float s = 0.0f;
        for (int i = tid; i < NROWS; i += 256)
            s += __logf(g_part[i] + g_part[i + NROWS]) - g_pos[i];
        #pragma unroll
        for (int o = 16; o; o >>= 1) s += __shfl_xor_sync(0xffffffffu, s, o);
        if (lane == 0) wsum[wid] = s;
        __syncthreads();
        if (wid == 0) {
            float v = (lane < 8) ? wsum[lane] : 0.0f;
            #pragma unroll
            for (int o = 4; o; o >>= 1) v += __shfl_xor_sync(0xffffffffu, v, o);
            if (lane == 0) out[0] = v * (1.0f / (float)NROWS);
        }
    }
}

// ---------------- launch ----------------
extern "C" void kernel_launch(void* const* d_in, const int* in_sizes, int n_in,
                              void* d_out, int out_size) {
    const float* A = (const float*)d_in[0];
    const float* P = (const float*)d_in[1];
    int dev = 0, nsm = 148;
    cudaGetDevice(&dev);
    cudaDeviceGetAttribute(&nsm, cudaDevAttrMultiProcessorCount, dev);
    int G = nsm * 2;
    int Q = NTRI / G, R = NTRI % G;
    cudaFuncSetAttribute(mma_kernel, cudaFuncAttributeMaxDynamicSharedMemorySize, SMEM_TOTAL);
    prep_kernel<<<NROWS / 16, 256>>>(A, P, (float*)d_out);
    mma_kernel<<<G, 256, SMEM_TOTAL>>>(Q, R, G, (float*)d_out);
}